// round 15
// baseline (speedup 1.0000x reference)
#include <cuda_runtime.h>
#include <cuda_fp16.h>
#include <math.h>
#include <stdint.h>

// Problem constants
#define L_SEQ 2048
#define DIMC  1024
#define NST   16
#define BATCH 2
#define MROWS (BATCH * L_SEQ)     // 4096
#define XDW   (2 * NST + DIMC)    // 1056
#define KDIM  1024
#define KTILES 32                 // KDIM / 32
#define PADH  40                  // smem halves per row (32 + 8 pad)
#define SEG   (128 * PADH)        // halves per operand buffer per stage
#define NSTAGE 4
#define NSM   148
#define NCH   8                   // scan chunks
#define CHL   (L_SEQ / NCH)       // 256

// ---------------------------------------------------------------------------
// Device scratch
// ---------------------------------------------------------------------------
__device__ float g_xz[(size_t)MROWS * 2048];
__device__ float g_xc[(size_t)MROWS * DIMC];
__device__ float g_xdbl[(size_t)MROWS * XDW];
__device__ float g_zsT[(size_t)BATCH * DIMC * L_SEQ];
__device__ float g_dtxc[(size_t)BATCH * DIMC * L_SEQ * 2];
__device__ float g_bc[(size_t)BATCH * (L_SEQ / 2) * NST * 4];
__device__ float g_P[(size_t)1024 * NCH * 32];
__device__ float g_Q[(size_t)1024 * NCH * 32];
__device__ float g_HS[(size_t)1024 * NCH * 32];

// fp16 hi/lo split operand buffers
__device__ __half g_xh[(size_t)MROWS * KDIM],   g_xl[(size_t)MROWS * KDIM];
__device__ __half g_wih[(size_t)2048 * KDIM],   g_wil[(size_t)2048 * KDIM];
__device__ __half g_wxh[(size_t)XDW * KDIM],    g_wxl[(size_t)XDW * KDIM];
__device__ __half g_woh[(size_t)DIMC * KDIM],   g_wol[(size_t)DIMC * KDIM];
__device__ __half g_xch[(size_t)MROWS * DIMC],  g_xcl[(size_t)MROWS * DIMC];
__device__ __half g_yh[(size_t)MROWS * DIMC],   g_yl[(size_t)MROWS * DIMC];

// ---------------------------------------------------------------------------
// PTX helpers
// ---------------------------------------------------------------------------
__device__ __forceinline__ uint32_t smem_u32(const void* p) {
    uint32_t a;
    asm("{ .reg .u64 t; cvta.to.shared.u64 t, %1; cvt.u32.u64 %0, t; }" : "=r"(a) : "l"(p));
    return a;
}
__device__ __forceinline__ void cp_async16(uint32_t dst, const void* src, int src_bytes) {
    asm volatile("cp.async.cg.shared.global [%0], [%1], 16, %2;"
                 :: "r"(dst), "l"(src), "r"(src_bytes));
}
#define CP_COMMIT() asm volatile("cp.async.commit_group;" ::: "memory")
#define CP_WAIT(n)  asm volatile("cp.async.wait_group %0;" :: "n"(n) : "memory")

__device__ __forceinline__ void mma_f16_f32acc(float c[4], const uint32_t a[4], const uint32_t b[2]) {
    asm volatile(
        "mma.sync.aligned.m16n8k16.row.col.f32.f16.f16.f32 "
        "{%0,%1,%2,%3}, {%4,%5,%6,%7}, {%8,%9}, {%0,%1,%2,%3};"
        : "+f"(c[0]), "+f"(c[1]), "+f"(c[2]), "+f"(c[3])
        : "r"(a[0]), "r"(a[1]), "r"(a[2]), "r"(a[3]), "r"(b[0]), "r"(b[1]));
}
__device__ __forceinline__ void mma_f16_f16acc(uint32_t c[2], const uint32_t a[4], const uint32_t b[2]) {
    asm volatile(
        "mma.sync.aligned.m16n8k16.row.col.f16.f16.f16.f16 "
        "{%0,%1}, {%2,%3,%4,%5}, {%6,%7}, {%0,%1};"
        : "+r"(c[0]), "+r"(c[1])
        : "r"(a[0]), "r"(a[1]), "r"(a[2]), "r"(a[3]), "r"(b[0]), "r"(b[1]));
}
__device__ __forceinline__ void ldsm_x4(uint32_t& r0, uint32_t& r1, uint32_t& r2, uint32_t& r3,
                                        uint32_t addr) {
    asm volatile("ldmatrix.sync.aligned.m8n8.x4.shared.b16 {%0,%1,%2,%3}, [%4];"
                 : "=r"(r0), "=r"(r1), "=r"(r2), "=r"(r3) : "r"(addr));
}

// ---------------------------------------------------------------------------
// Fused fp32 -> (hi, lo) fp16 split for x + 3 weight matrices
// ---------------------------------------------------------------------------
#define N4_X  (MROWS * KDIM / 4)
#define N4_WI (2048 * KDIM / 4)
#define N4_WX (XDW * KDIM / 4)
#define N4_WO (DIMC * KDIM / 4)
#define N4_TOT (N4_X + N4_WI + N4_WX + N4_WO)

__global__ void split_all_kernel(const float* __restrict__ x,
                                 const float* __restrict__ wi,
                                 const float* __restrict__ wx,
                                 const float* __restrict__ wo,
                                 __half* xh, __half* xl, __half* wih, __half* wil,
                                 __half* wxh, __half* wxl, __half* woh, __half* wol)
{
    int i = blockIdx.x * blockDim.x + threadIdx.x;
    if (i >= N4_TOT) return;
    const float* src; __half* hi; __half* lo; int j;
    if (i < N4_X)                   { src = x;  hi = xh;  lo = xl;  j = i; }
    else if (i < N4_X + N4_WI)      { src = wi; hi = wih; lo = wil; j = i - N4_X; }
    else if (i < N4_X + N4_WI + N4_WX) { src = wx; hi = wxh; lo = wxl; j = i - N4_X - N4_WI; }
    else                            { src = wo; hi = woh; lo = wol; j = i - N4_X - N4_WI - N4_WX; }

    float4 v = ((const float4*)src)[j];
    __half h0 = __float2half_rn(v.x), h1 = __float2half_rn(v.y);
    __half h2 = __float2half_rn(v.z), h3 = __float2half_rn(v.w);
    ((half2*)hi)[2 * j]     = __halves2half2(h0, h1);
    ((half2*)hi)[2 * j + 1] = __halves2half2(h2, h3);
    ((half2*)lo)[2 * j] = __halves2half2(
        __float2half_rn(v.x - __half2float(h0)), __float2half_rn(v.y - __half2float(h1)));
    ((half2*)lo)[2 * j + 1] = __halves2half2(
        __float2half_rn(v.z - __half2float(h2)), __float2half_rn(v.w - __half2float(h3)));
}

// ---------------------------------------------------------------------------
// Persistent fp16-split GEMM (R14 config, measured best)
// ---------------------------------------------------------------------------
__device__ __forceinline__ void load_tile(uint32_t s_st, int stage,
    const __half* Ahp, const __half* Alp, const __half* Bhp, const __half* Blp,
    int ko, int bbytes)
{
    const uint32_t so = (uint32_t)stage * (4u * SEG * 2u);
    cp_async16(s_st + so + 0u * SEG * 2u, Ahp + ko, 16);
    cp_async16(s_st + so + 1u * SEG * 2u, Alp + ko, 16);
    cp_async16(s_st + so + 2u * SEG * 2u, Bhp + ko, bbytes);
    cp_async16(s_st + so + 3u * SEG * 2u, Blp + ko, bbytes);
}

__global__ __launch_bounds__(512, 1)
void gemm_f16s(const __half* __restrict__ Ah, const __half* __restrict__ Al,
               const __half* __restrict__ Bh, const __half* __restrict__ Bl,
               float* __restrict__ C, int N, int ldc, int bnTiles, int totalTiles)
{
    extern __shared__ __half sh[];
    const uint32_t smem_base = smem_u32(sh);

    const int tid = threadIdx.x;
    const int wid = tid >> 5;
    const int lane = tid & 31;

    const int r = tid >> 2;
    const int hc = (tid & 3) << 3;
    const uint32_t s_st = smem_base + ((uint32_t)r * PADH + hc) * 2u;
    const int wm = (wid & 3) << 5;
    const int wn = (wid >> 2) << 5;
    const int g = lane >> 2;
    const int tig = lane & 3;

    uint32_t aAddr[2];
#pragma unroll
    for (int mi = 0; mi < 2; mi++) {
        int row = wm + mi * 16 + (lane & 15);
        aAddr[mi] = ((uint32_t)row * PADH + ((lane >> 4) << 3)) * 2u;
    }
    uint32_t bAddr[2];
#pragma unroll
    for (int p = 0; p < 2; p++) {
        int n = wn + p * 16 + (lane & 7) + ((lane >> 4) << 3);
        bAddr[p] = ((uint32_t)n * PADH + (((lane >> 3) & 1) << 3)) * 2u;
    }

    for (int tile = blockIdx.x; tile < totalTiles; tile += gridDim.x) {
        const int by = tile / bnTiles;
        const int bx = tile - by * bnTiles;
        const int bm = by << 7;
        const int bn = bx << 7;

        const __half* Ahp = Ah + (size_t)(bm + r) * KDIM + hc;
        const __half* Alp = Al + (size_t)(bm + r) * KDIM + hc;
        const int brow = bn + r;
        const int bbytes = (brow < N) ? 16 : 0;
        const __half* Bhp = Bh + (size_t)brow * KDIM + hc;
        const __half* Blp = Bl + (size_t)brow * KDIM + hc;

        float acc[2][4][4];
        uint32_t hacc[2][4][2];
#pragma unroll
        for (int mi = 0; mi < 2; mi++)
#pragma unroll
            for (int ni = 0; ni < 4; ni++) {
#pragma unroll
                for (int q = 0; q < 4; q++) acc[mi][ni][q] = 0.f;
                hacc[mi][ni][0] = 0u; hacc[mi][ni][1] = 0u;
            }

        load_tile(s_st, 0, Ahp, Alp, Bhp, Blp, 0, bbytes);
        CP_COMMIT();
        load_tile(s_st, 1, Ahp, Alp, Bhp, Blp, 32, bbytes);
        CP_COMMIT();

        for (int kt = 0; kt < KTILES; kt++) {
            if (kt + 2 < KTILES) {
                load_tile(s_st, (kt + 2) & (NSTAGE - 1), Ahp, Alp, Bhp, Blp,
                          (kt + 2) * 32, bbytes);
                CP_COMMIT();
                CP_WAIT(2);
            } else {
                CP_WAIT(0);
            }
            __syncthreads();

            const uint32_t stage_base =
                smem_base + (uint32_t)(kt & (NSTAGE - 1)) * (4u * SEG * 2u);
            const uint32_t bAh = stage_base;
            const uint32_t bAl = stage_base + SEG * 2u;
            const uint32_t bBh = stage_base + 2u * SEG * 2u;
            const uint32_t bBl = stage_base + 3u * SEG * 2u;

#pragma unroll
            for (int ks = 0; ks < 2; ks++) {
                const uint32_t kso = (uint32_t)ks * 32u;
                uint32_t bh[4][2], bl[4][2];
                ldsm_x4(bh[0][0], bh[0][1], bh[1][0], bh[1][1], bBh + bAddr[0] + kso);
                ldsm_x4(bh[2][0], bh[2][1], bh[3][0], bh[3][1], bBh + bAddr[1] + kso);
                ldsm_x4(bl[0][0], bl[0][1], bl[1][0], bl[1][1], bBl + bAddr[0] + kso);
                ldsm_x4(bl[2][0], bl[2][1], bl[3][0], bl[3][1], bBl + bAddr[1] + kso);
#pragma unroll
                for (int mi = 0; mi < 2; mi++) {
                    uint32_t ah[4], al[4];
                    ldsm_x4(ah[0], ah[1], ah[2], ah[3], bAh + aAddr[mi] + kso);
                    ldsm_x4(al[0], al[1], al[2], al[3], bAl + aAddr[mi] + kso);
#pragma unroll
                    for (int ni = 0; ni < 4; ni++) {
                        mma_f16_f32acc(acc[mi][ni], ah, bh[ni]);
                        mma_f16_f16acc(hacc[mi][ni], ah, bl[ni]);
                        mma_f16_f16acc(hacc[mi][ni], al, bh[ni]);
                    }
                }
            }
        }

#pragma unroll
        for (int mi = 0; mi < 2; mi++) {
            const int row = bm + wm + mi * 16 + g;
#pragma unroll
            for (int ni = 0; ni < 4; ni++) {
                const int col = bn + wn + ni * 8 + tig * 2;
                if (col < N) {
                    float2 c0 = __half22float2(*(half2*)&hacc[mi][ni][0]);
                    float2 c1 = __half22float2(*(half2*)&hacc[mi][ni][1]);
                    *(float2*)(C + (size_t)row * ldc + col) =
                        make_float2(acc[mi][ni][0] + c0.x, acc[mi][ni][1] + c0.y);
                    *(float2*)(C + (size_t)(row + 8) * ldc + col) =
                        make_float2(acc[mi][ni][2] + c1.x, acc[mi][ni][3] + c1.y);
                }
            }
        }
    }
}

// ---------------------------------------------------------------------------
// Depthwise causal conv(k=4) + bias + SiLU -> g_xc (+ hi/lo halves);
// SiLU(z) -> g_zsT (b,d,l)
// ---------------------------------------------------------------------------
__global__ void conv_kernel(const float* __restrict__ xz,
                            const float* __restrict__ cw,
                            const float* __restrict__ cb,
                            float* __restrict__ xc,
                            __half* __restrict__ xch,
                            __half* __restrict__ xcl,
                            float* __restrict__ zsT)
{
    __shared__ float xs[35][33];
    __shared__ float zs[32][33];
    const int b = blockIdx.z;
    const int l0 = blockIdx.y << 5;
    const int d0 = blockIdx.x << 5;
    const int t = threadIdx.x;
    const int c = t & 31;
    const int r0 = t >> 5;

    for (int r = r0; r < 35; r += 8) {
        int l = l0 - 3 + r;
        xs[r][c] = (l >= 0) ? xz[((size_t)(b * L_SEQ + l) << 11) + d0 + c] : 0.f;
    }
    for (int r = r0; r < 32; r += 8) {
        float v = xz[((size_t)(b * L_SEQ + l0 + r) << 11) + DIMC + d0 + c];
        zs[r][c] = __fdividef(v, 1.f + __expf(-v));
    }
    __syncthreads();

    const float4 w = *(const float4*)(cw + (size_t)(d0 + c) * 4);
    const float bias = cb[d0 + c];
    for (int r = r0; r < 32; r += 8) {
        float v = w.x * xs[r][c] + w.y * xs[r + 1][c] + w.z * xs[r + 2][c]
                + w.w * xs[r + 3][c] + bias;
        v = __fdividef(v, 1.f + __expf(-v));
        const size_t idx = (size_t)(b * L_SEQ + l0 + r) * DIMC + d0 + c;
        xc[idx] = v;
        __half hv = __float2half_rn(v);
        xch[idx] = hv;
        xcl[idx] = __float2half_rn(v - __half2float(hv));
    }
    __syncthreads();
    for (int r = r0; r < 32; r += 8) {
        zsT[(size_t)((b << 10) + d0 + r) * L_SEQ + l0 + c] = zs[c][r];
    }
}

// ---------------------------------------------------------------------------
// Build (b,d,l,{softplus(dt), xc}) interleaved stream + pack B/C (fused)
// ---------------------------------------------------------------------------
__global__ void dtxc_kernel(const float* __restrict__ xdbl,
                            const float* __restrict__ xc,
                            float* __restrict__ dtxc,
                            float* __restrict__ bc)
{
    __shared__ float sdt[32][33];
    __shared__ float sxc[32][33];
    const int b = blockIdx.z;
    const int l0 = blockIdx.y << 5;
    const int d0 = blockIdx.x << 5;
    const int t = threadIdx.x;
    const int c = t & 31;
    const int r0 = t >> 5;

    for (int r = r0; r < 32; r += 8) {
        float v = xdbl[(size_t)(b * L_SEQ + l0 + r) * XDW + 2 * NST + d0 + c];
        sdt[r][c] = (v > 15.f) ? v : log1pf(__expf(v));
        sxc[r][c] = xc[(size_t)(b * L_SEQ + l0 + r) * DIMC + d0 + c];
    }
    if (d0 == 0) {
        int n = t & 15;
        int l2 = (l0 >> 1) + (t >> 4);
        const float* p = xdbl + (size_t)(b * L_SEQ + 2 * l2) * XDW;
        float4 v = make_float4(p[n], p[NST + n], p[XDW + n], p[XDW + NST + n]);
        *(float4*)(bc + ((size_t)b * (L_SEQ / 2) * NST + (size_t)l2 * NST + n) * 4) = v;
    }
    __syncthreads();
    for (int r = r0; r < 32; r += 8) {
        float2 v = make_float2(sdt[c][r], sxc[c][r]);
        *(float2*)(dtxc + ((size_t)((b << 10) + d0 + r) * L_SEQ + l0 + c) * 2) = v;
    }
}

// ---------------------------------------------------------------------------
// Chunked scan, phase 1: per-chunk (P = prod dA, Q = partial h) from h=0.
// warp -> (wd, chunk). 8192 warps.
// ---------------------------------------------------------------------------
__global__ void scan_phase1(const float* __restrict__ dtxc,
                            const float* __restrict__ bc,
                            float* __restrict__ gP, float* __restrict__ gQ)
{
    const int warp = (blockIdx.x * blockDim.x + threadIdx.x) >> 5;
    const int lane = threadIdx.x & 31;
    const int ch = warp & (NCH - 1);
    const int wd = warp >> 3;          // 0..1023
    const int b = wd >> 9;
    const int d = ((wd & 511) << 1) + (lane >> 4);
    const int n = lane & 15;
    const float An = -(float)(n + 1);

    const size_t rowoff = (size_t)((b << 10) + d) * L_SEQ;
    const int l0 = ch << 8;
    const float* dxp = dtxc + rowoff * 2 + 2 * l0;
    const float* bcp = bc + ((size_t)b * (L_SEQ / 2) * NST + n) * 4 + (size_t)(l0 >> 1) * 64;

    float h = 0.f, P = 1.f;
    for (int i = 0; i < CHL; i += 4) {
        float4 v0 = *(const float4*)(dxp + 2 * i);
        float4 v1 = *(const float4*)(dxp + 2 * i + 4);
        const float* q = bcp + (size_t)(i >> 1) * 64;
        float4 p01 = *(const float4*)q;
        float4 p23 = *(const float4*)(q + 64);
        float dA;
        dA = __expf(An * v0.x); h = fmaf(h, dA, v0.x * v0.y * p01.x); P *= dA;
        dA = __expf(An * v0.z); h = fmaf(h, dA, v0.z * v0.w * p01.z); P *= dA;
        dA = __expf(An * v1.x); h = fmaf(h, dA, v1.x * v1.y * p23.x); P *= dA;
        dA = __expf(An * v1.z); h = fmaf(h, dA, v1.z * v1.w * p23.z); P *= dA;
    }
    const size_t o = ((size_t)wd * NCH + ch) * 32 + lane;
    gP[o] = P;
    gQ[o] = h;
}

// ---------------------------------------------------------------------------
// Chunked scan, combine: sequential over 8 chunks per (wd, lane).
// ---------------------------------------------------------------------------
__global__ void scan_combine(const float* __restrict__ gP,
                             const float* __restrict__ gQ,
                             float* __restrict__ gHS)
{
    int idx = blockIdx.x * blockDim.x + threadIdx.x;   // 32768 total
    int lane = idx & 31;
    int wd = idx >> 5;
    float h = 0.f;
#pragma unroll
    for (int ch = 0; ch < NCH; ch++) {
        size_t o = ((size_t)wd * NCH + ch) * 32 + lane;
        gHS[o] = h;
        h = h * gP[o] + gQ[o];
    }
}

// ---------------------------------------------------------------------------
// Chunked scan, phase 2: full scan per chunk from h_start, emit y hi/lo.
// ---------------------------------------------------------------------------
__device__ __forceinline__ void scan_step4(
    float& h, float An, float Dv, int lane,
    const float4& cv0, const float4& cv1, const float4& cb01, const float4& cb23,
    const float4& cz, __half* yh, __half* yl, size_t ybase, int l)
{
    float4 yv;
    {
        float dA = __expf(An * cv0.x);
        h = fmaf(h, dA, cv0.x * cv0.y * cb01.x);
        float pr = h * cb01.y;
        pr += __shfl_xor_sync(0xffffffffu, pr, 1);
        pr += __shfl_xor_sync(0xffffffffu, pr, 2);
        pr += __shfl_xor_sync(0xffffffffu, pr, 4);
        pr += __shfl_xor_sync(0xffffffffu, pr, 8);
        yv.x = fmaf(Dv, cv0.y, pr) * cz.x;
    }
    {
        float dA = __expf(An * cv0.z);
        h = fmaf(h, dA, cv0.z * cv0.w * cb01.z);
        float pr = h * cb01.w;
        pr += __shfl_xor_sync(0xffffffffu, pr, 1);
        pr += __shfl_xor_sync(0xffffffffu, pr, 2);
        pr += __shfl_xor_sync(0xffffffffu, pr, 4);
        pr += __shfl_xor_sync(0xffffffffu, pr, 8);
        yv.y = fmaf(Dv, cv0.w, pr) * cz.y;
    }
    {
        float dA = __expf(An * cv1.x);
        h = fmaf(h, dA, cv1.x * cv1.y * cb23.x);
        float pr = h * cb23.y;
        pr += __shfl_xor_sync(0xffffffffu, pr, 1);
        pr += __shfl_xor_sync(0xffffffffu, pr, 2);
        pr += __shfl_xor_sync(0xffffffffu, pr, 4);
        pr += __shfl_xor_sync(0xffffffffu, pr, 8);
        yv.z = fmaf(Dv, cv1.y, pr) * cz.z;
    }
    {
        float dA = __expf(An * cv1.z);
        h = fmaf(h, dA, cv1.z * cv1.w * cb23.z);
        float pr = h * cb23.w;
        pr += __shfl_xor_sync(0xffffffffu, pr, 1);
        pr += __shfl_xor_sync(0xffffffffu, pr, 2);
        pr += __shfl_xor_sync(0xffffffffu, pr, 4);
        pr += __shfl_xor_sync(0xffffffffu, pr, 8);
        yv.w = fmaf(Dv, cv1.w, pr) * cz.w;
    }
    float u0 = __shfl_sync(0xffffffffu, yv.x, 16);
    float u1 = __shfl_sync(0xffffffffu, yv.y, 16);
    float u2 = __shfl_sync(0xffffffffu, yv.z, 16);
    float u3 = __shfl_sync(0xffffffffu, yv.w, 16);
    if (lane == 0) {
        float a[4] = {yv.x, yv.y, yv.z, yv.w};
        float bq[4] = {u0, u1, u2, u3};
#pragma unroll
        for (int q = 0; q < 4; q++) {
            __half ha = __float2half_rn(a[q]);
            __half hb = __float2half_rn(bq[q]);
            *(half2*)(yh + ybase + (size_t)(l + q) * DIMC) = __halves2half2(ha, hb);
            *(half2*)(yl + ybase + (size_t)(l + q) * DIMC) = __halves2half2(
                __float2half_rn(a[q] - __half2float(ha)),
                __float2half_rn(bq[q] - __half2float(hb)));
        }
    }
}

__global__ void scan_phase2(const float* __restrict__ dtxc,
                            const float* __restrict__ bc,
                            const float* __restrict__ zsT,
                            const float* __restrict__ Dp,
                            const float* __restrict__ gHS,
                            __half* __restrict__ yh,
                            __half* __restrict__ yl)
{
    const int warp = (blockIdx.x * blockDim.x + threadIdx.x) >> 5;
    const int lane = threadIdx.x & 31;
    const int ch = warp & (NCH - 1);
    const int wd = warp >> 3;
    const int b = wd >> 9;
    const int d = ((wd & 511) << 1) + (lane >> 4);
    const int n = lane & 15;
    const float An = -(float)(n + 1);
    const bool root = (n == 0);

    const size_t rowoff = (size_t)((b << 10) + d) * L_SEQ;
    const float* dxp = dtxc + rowoff * 2;
    const float* zp = zsT + rowoff;
    const float* bcp = bc + ((size_t)b * (L_SEQ / 2) * NST + n) * 4;
    const size_t ybase = ((size_t)b * L_SEQ) * DIMC + ((wd & 511) << 1);
    const float Dv = Dp[d];
    float h = gHS[((size_t)wd * NCH + ch) * 32 + lane];

    const int l0 = ch << 8;
    const int lend = l0 + CHL;
    const float4 z4 = make_float4(0.f, 0.f, 0.f, 0.f);
    float4 a_v0 = *(const float4*)(dxp + 2 * l0);
    float4 a_v1 = *(const float4*)(dxp + 2 * l0 + 4);
    const float* q0 = bcp + (size_t)(l0 >> 1) * 64;
    float4 a_p01 = *(const float4*)q0;
    float4 a_p23 = *(const float4*)(q0 + 64);
    float4 a_z  = root ? *(const float4*)(zp + l0) : z4;
    float4 b_v0 = *(const float4*)(dxp + 2 * (l0 + 4));
    float4 b_v1 = *(const float4*)(dxp + 2 * (l0 + 4) + 4);
    const float* q1 = bcp + (size_t)((l0 + 4) >> 1) * 64;
    float4 b_p01 = *(const float4*)q1;
    float4 b_p23 = *(const float4*)(q1 + 64);
    float4 b_z  = root ? *(const float4*)(zp + l0 + 4) : z4;

    for (int l = l0; l < lend; l += 8) {
        float4 cv0 = a_v0, cv1 = a_v1, cb01 = a_p01, cb23 = a_p23, cz = a_z;
        if (l + 8 < L_SEQ) {
            a_v0 = *(const float4*)(dxp + 2 * (l + 8));
            a_v1 = *(const float4*)(dxp + 2 * (l + 8) + 4);
            const float* q = bcp + (size_t)((l + 8) >> 1) * 64;
            a_p01 = *(const float4*)q;
            a_p23 = *(const float4*)(q + 64);
            if (root) a_z = *(const float4*)(zp + l + 8);
        }
        scan_step4(h, An, Dv, lane, cv0, cv1, cb01, cb23, cz, yh, yl, ybase, l);

        cv0 = b_v0; cv1 = b_v1; cb01 = b_p01; cb23 = b_p23; cz = b_z;
        if (l + 12 < L_SEQ) {
            b_v0 = *(const float4*)(dxp + 2 * (l + 12));
            b_v1 = *(const float4*)(dxp + 2 * (l + 12) + 4);
            const float* q = bcp + (size_t)((l + 12) >> 1) * 64;
            b_p01 = *(const float4*)q;
            b_p23 = *(const float4*)(q + 64);
            if (root) b_z = *(const float4*)(zp + l + 12);
        }
        scan_step4(h, An, Dv, lane, cv0, cv1, cb01, cb23, cz, yh, yl, ybase, l + 4);
    }
}

// ---------------------------------------------------------------------------
// kernel_launch
// ---------------------------------------------------------------------------
extern "C" void kernel_launch(void* const* d_in, const int* in_sizes, int n_in,
                              void* d_out, int out_size)
{
    (void)in_sizes; (void)n_in; (void)out_size;
    const float* x          = (const float*)d_in[0];
    const float* in_proj_w  = (const float*)d_in[1];
    const float* conv_w     = (const float*)d_in[2];
    const float* conv_b     = (const float*)d_in[3];
    const float* x_proj_w   = (const float*)d_in[4];
    const float* D_param    = (const float*)d_in[5];
    const float* out_proj_w = (const float*)d_in[6];
    float* out = (float*)d_out;

    float *xz, *xc, *xdbl, *zsT, *dtxc, *bcp, *gP, *gQ, *gHS;
    __half *xh, *xl, *wih, *wil, *wxh, *wxl, *woh, *wol, *xch, *xcl, *yh, *yl;
    cudaGetSymbolAddress((void**)&xz, g_xz);
    cudaGetSymbolAddress((void**)&xc, g_xc);
    cudaGetSymbolAddress((void**)&xdbl, g_xdbl);
    cudaGetSymbolAddress((void**)&zsT, g_zsT);
    cudaGetSymbolAddress((void**)&dtxc, g_dtxc);
    cudaGetSymbolAddress((void**)&bcp, g_bc);
    cudaGetSymbolAddress((void**)&gP, g_P);
    cudaGetSymbolAddress((void**)&gQ, g_Q);
    cudaGetSymbolAddress((void**)&gHS, g_HS);
    cudaGetSymbolAddress((void**)&xh, g_xh);   cudaGetSymbolAddress((void**)&xl, g_xl);
    cudaGetSymbolAddress((void**)&wih, g_wih); cudaGetSymbolAddress((void**)&wil, g_wil);
    cudaGetSymbolAddress((void**)&wxh, g_wxh); cudaGetSymbolAddress((void**)&wxl, g_wxl);
    cudaGetSymbolAddress((void**)&woh, g_woh); cudaGetSymbolAddress((void**)&wol, g_wol);
    cudaGetSymbolAddress((void**)&xch, g_xch); cudaGetSymbolAddress((void**)&xcl, g_xcl);
    cudaGetSymbolAddress((void**)&yh, g_yh);   cudaGetSymbolAddress((void**)&yl, g_yl);

    const int SMEM_BYTES = NSTAGE * 4 * SEG * 2;  // 163840
    cudaFuncSetAttribute(gemm_f16s, cudaFuncAttributeMaxDynamicSharedMemorySize, SMEM_BYTES);

    // 0) split inputs + weights to fp16 hi/lo
    split_all_kernel<<<(N4_TOT + 255) / 256, 256>>>(x, in_proj_w, x_proj_w, out_proj_w,
                                                    xh, xl, wih, wil, wxh, wxl, woh, wol);

    // 1) xz = x @ in_proj_w^T   (4096 x 2048): 512 tiles, persistent
    gemm_f16s<<<NSM, 512, SMEM_BYTES>>>(xh, xl, wih, wil, xz, 2048, 2048, 16, 512);

    // 2) depthwise conv + silu (+ hi/lo emit), silu(z) transpose
    conv_kernel<<<dim3(32, 64, 2), 256>>>(xz, conv_w, conv_b, xc, xch, xcl, zsT);

    // 3) x_dbl = xc @ x_proj_w^T  (4096 x 1056): 288 tiles
    gemm_f16s<<<NSM, 512, SMEM_BYTES>>>(xch, xcl, wxh, wxl, xdbl, 1056, 1056, 9, 288);

    // 4) pack scan streams (dtxc + bc fused)
    dtxc_kernel<<<dim3(32, 64, 2), 256>>>(xdbl, xc, dtxc, bcp);

    // 5) chunked selective scan: phase1 -> combine -> phase2
    scan_phase1<<<1024, 256>>>(dtxc, bcp, gP, gQ);
    scan_combine<<<128, 256>>>(gP, gQ, gHS);
    scan_phase2<<<1024, 256>>>(dtxc, bcp, zsT, D_param, gHS, yh, yl);

    // 6) out = y @ out_proj_w^T  (4096 x 1024): 256 tiles
    gemm_f16s<<<NSM, 512, SMEM_BYTES>>>(yh, yl, woh, wol, out, 1024, 1024, 8, 256);
}

// round 16
// speedup vs baseline: 1.0554x; 1.0554x over previous
#include <cuda_runtime.h>
#include <cuda_fp16.h>
#include <math.h>
#include <stdint.h>

// Problem constants
#define L_SEQ 2048
#define DIMC  1024
#define NST   16
#define BATCH 2
#define MROWS (BATCH * L_SEQ)     // 4096
#define XDW   (2 * NST + DIMC)    // 1056
#define KDIM  1024
#define KTILES 32                 // KDIM / 32
#define PADH  40                  // smem halves per row (32 + 8 pad)
#define SEG   (128 * PADH)        // halves per operand buffer per stage
#define NSTAGE 4
#define NSM   148

// ---------------------------------------------------------------------------
// Device scratch
// ---------------------------------------------------------------------------
__device__ float g_xz[(size_t)MROWS * 2048];
__device__ float g_xdbl[(size_t)MROWS * XDW];
__device__ float g_zsT[(size_t)BATCH * DIMC * L_SEQ];
__device__ float g_dtxc[(size_t)BATCH * DIMC * L_SEQ * 2];
__device__ float g_bc[(size_t)BATCH * (L_SEQ / 2) * NST * 4];

// fp16 hi/lo split operand buffers
__device__ __half g_xh[(size_t)MROWS * KDIM],   g_xl[(size_t)MROWS * KDIM];
__device__ __half g_wih[(size_t)2048 * KDIM],   g_wil[(size_t)2048 * KDIM];
__device__ __half g_wxh[(size_t)XDW * KDIM],    g_wxl[(size_t)XDW * KDIM];
__device__ __half g_woh[(size_t)DIMC * KDIM],   g_wol[(size_t)DIMC * KDIM];
__device__ __half g_xch[(size_t)MROWS * DIMC],  g_xcl[(size_t)MROWS * DIMC];
__device__ __half g_yh[(size_t)MROWS * DIMC],   g_yl[(size_t)MROWS * DIMC];

// ---------------------------------------------------------------------------
// PTX helpers
// ---------------------------------------------------------------------------
__device__ __forceinline__ uint32_t smem_u32(const void* p) {
    uint32_t a;
    asm("{ .reg .u64 t; cvta.to.shared.u64 t, %1; cvt.u32.u64 %0, t; }" : "=r"(a) : "l"(p));
    return a;
}
__device__ __forceinline__ void cp_async16(uint32_t dst, const void* src, int src_bytes) {
    asm volatile("cp.async.cg.shared.global [%0], [%1], 16, %2;"
                 :: "r"(dst), "l"(src), "r"(src_bytes));
}
#define CP_COMMIT() asm volatile("cp.async.commit_group;" ::: "memory")
#define CP_WAIT(n)  asm volatile("cp.async.wait_group %0;" :: "n"(n) : "memory")

__device__ __forceinline__ void mma_f16_f32acc(float c[4], const uint32_t a[4], const uint32_t b[2]) {
    asm volatile(
        "mma.sync.aligned.m16n8k16.row.col.f32.f16.f16.f32 "
        "{%0,%1,%2,%3}, {%4,%5,%6,%7}, {%8,%9}, {%0,%1,%2,%3};"
        : "+f"(c[0]), "+f"(c[1]), "+f"(c[2]), "+f"(c[3])
        : "r"(a[0]), "r"(a[1]), "r"(a[2]), "r"(a[3]), "r"(b[0]), "r"(b[1]));
}
__device__ __forceinline__ void mma_f16_f16acc(uint32_t c[2], const uint32_t a[4], const uint32_t b[2]) {
    asm volatile(
        "mma.sync.aligned.m16n8k16.row.col.f16.f16.f16.f16 "
        "{%0,%1}, {%2,%3,%4,%5}, {%6,%7}, {%0,%1};"
        : "+r"(c[0]), "+r"(c[1])
        : "r"(a[0]), "r"(a[1]), "r"(a[2]), "r"(a[3]), "r"(b[0]), "r"(b[1]));
}
__device__ __forceinline__ void ldsm_x4(uint32_t& r0, uint32_t& r1, uint32_t& r2, uint32_t& r3,
                                        uint32_t addr) {
    asm volatile("ldmatrix.sync.aligned.m8n8.x4.shared.b16 {%0,%1,%2,%3}, [%4];"
                 : "=r"(r0), "=r"(r1), "=r"(r2), "=r"(r3) : "r"(addr));
}

// ---------------------------------------------------------------------------
// Fused fp32 -> (hi, lo) fp16 split for x + 3 weight matrices
// ---------------------------------------------------------------------------
#define N4_X  (MROWS * KDIM / 4)
#define N4_WI (2048 * KDIM / 4)
#define N4_WX (XDW * KDIM / 4)
#define N4_WO (DIMC * KDIM / 4)
#define N4_TOT (N4_X + N4_WI + N4_WX + N4_WO)

__global__ void split_all_kernel(const float* __restrict__ x,
                                 const float* __restrict__ wi,
                                 const float* __restrict__ wx,
                                 const float* __restrict__ wo,
                                 __half* xh, __half* xl, __half* wih, __half* wil,
                                 __half* wxh, __half* wxl, __half* woh, __half* wol)
{
    int i = blockIdx.x * blockDim.x + threadIdx.x;
    if (i >= N4_TOT) return;
    const float* src; __half* hi; __half* lo; int j;
    if (i < N4_X)                   { src = x;  hi = xh;  lo = xl;  j = i; }
    else if (i < N4_X + N4_WI)      { src = wi; hi = wih; lo = wil; j = i - N4_X; }
    else if (i < N4_X + N4_WI + N4_WX) { src = wx; hi = wxh; lo = wxl; j = i - N4_X - N4_WI; }
    else                            { src = wo; hi = woh; lo = wol; j = i - N4_X - N4_WI - N4_WX; }

    float4 v = ((const float4*)src)[j];
    __half h0 = __float2half_rn(v.x), h1 = __float2half_rn(v.y);
    __half h2 = __float2half_rn(v.z), h3 = __float2half_rn(v.w);
    ((half2*)hi)[2 * j]     = __halves2half2(h0, h1);
    ((half2*)hi)[2 * j + 1] = __halves2half2(h2, h3);
    ((half2*)lo)[2 * j] = __halves2half2(
        __float2half_rn(v.x - __half2float(h0)), __float2half_rn(v.y - __half2float(h1)));
    ((half2*)lo)[2 * j + 1] = __halves2half2(
        __float2half_rn(v.z - __half2float(h2)), __float2half_rn(v.w - __half2float(h3)));
}

// ---------------------------------------------------------------------------
// Persistent fp16-split GEMM (R14 config, measured best)
// ---------------------------------------------------------------------------
__device__ __forceinline__ void load_tile(uint32_t s_st, int stage,
    const __half* Ahp, const __half* Alp, const __half* Bhp, const __half* Blp,
    int ko, int bbytes)
{
    const uint32_t so = (uint32_t)stage * (4u * SEG * 2u);
    cp_async16(s_st + so + 0u * SEG * 2u, Ahp + ko, 16);
    cp_async16(s_st + so + 1u * SEG * 2u, Alp + ko, 16);
    cp_async16(s_st + so + 2u * SEG * 2u, Bhp + ko, bbytes);
    cp_async16(s_st + so + 3u * SEG * 2u, Blp + ko, bbytes);
}

__global__ __launch_bounds__(512, 1)
void gemm_f16s(const __half* __restrict__ Ah, const __half* __restrict__ Al,
               const __half* __restrict__ Bh, const __half* __restrict__ Bl,
               float* __restrict__ C, int N, int ldc, int bnTiles, int totalTiles)
{
    extern __shared__ __half sh[];
    const uint32_t smem_base = smem_u32(sh);

    const int tid = threadIdx.x;
    const int wid = tid >> 5;
    const int lane = tid & 31;

    const int r = tid >> 2;
    const int hc = (tid & 3) << 3;
    const uint32_t s_st = smem_base + ((uint32_t)r * PADH + hc) * 2u;
    const int wm = (wid & 3) << 5;
    const int wn = (wid >> 2) << 5;
    const int g = lane >> 2;
    const int tig = lane & 3;

    uint32_t aAddr[2];
#pragma unroll
    for (int mi = 0; mi < 2; mi++) {
        int row = wm + mi * 16 + (lane & 15);
        aAddr[mi] = ((uint32_t)row * PADH + ((lane >> 4) << 3)) * 2u;
    }
    uint32_t bAddr[2];
#pragma unroll
    for (int p = 0; p < 2; p++) {
        int n = wn + p * 16 + (lane & 7) + ((lane >> 4) << 3);
        bAddr[p] = ((uint32_t)n * PADH + (((lane >> 3) & 1) << 3)) * 2u;
    }

    for (int tile = blockIdx.x; tile < totalTiles; tile += gridDim.x) {
        const int by = tile / bnTiles;
        const int bx = tile - by * bnTiles;
        const int bm = by << 7;
        const int bn = bx << 7;

        const __half* Ahp = Ah + (size_t)(bm + r) * KDIM + hc;
        const __half* Alp = Al + (size_t)(bm + r) * KDIM + hc;
        const int brow = bn + r;
        const int bbytes = (brow < N) ? 16 : 0;
        const __half* Bhp = Bh + (size_t)brow * KDIM + hc;
        const __half* Blp = Bl + (size_t)brow * KDIM + hc;

        float acc[2][4][4];
        uint32_t hacc[2][4][2];
#pragma unroll
        for (int mi = 0; mi < 2; mi++)
#pragma unroll
            for (int ni = 0; ni < 4; ni++) {
#pragma unroll
                for (int q = 0; q < 4; q++) acc[mi][ni][q] = 0.f;
                hacc[mi][ni][0] = 0u; hacc[mi][ni][1] = 0u;
            }

        load_tile(s_st, 0, Ahp, Alp, Bhp, Blp, 0, bbytes);
        CP_COMMIT();
        load_tile(s_st, 1, Ahp, Alp, Bhp, Blp, 32, bbytes);
        CP_COMMIT();

        for (int kt = 0; kt < KTILES; kt++) {
            if (kt + 2 < KTILES) {
                load_tile(s_st, (kt + 2) & (NSTAGE - 1), Ahp, Alp, Bhp, Blp,
                          (kt + 2) * 32, bbytes);
                CP_COMMIT();
                CP_WAIT(2);
            } else {
                CP_WAIT(0);
            }
            __syncthreads();

            const uint32_t stage_base =
                smem_base + (uint32_t)(kt & (NSTAGE - 1)) * (4u * SEG * 2u);
            const uint32_t bAh = stage_base;
            const uint32_t bAl = stage_base + SEG * 2u;
            const uint32_t bBh = stage_base + 2u * SEG * 2u;
            const uint32_t bBl = stage_base + 3u * SEG * 2u;

#pragma unroll
            for (int ks = 0; ks < 2; ks++) {
                const uint32_t kso = (uint32_t)ks * 32u;
                uint32_t bh[4][2], bl[4][2];
                ldsm_x4(bh[0][0], bh[0][1], bh[1][0], bh[1][1], bBh + bAddr[0] + kso);
                ldsm_x4(bh[2][0], bh[2][1], bh[3][0], bh[3][1], bBh + bAddr[1] + kso);
                ldsm_x4(bl[0][0], bl[0][1], bl[1][0], bl[1][1], bBl + bAddr[0] + kso);
                ldsm_x4(bl[2][0], bl[2][1], bl[3][0], bl[3][1], bBl + bAddr[1] + kso);
#pragma unroll
                for (int mi = 0; mi < 2; mi++) {
                    uint32_t ah[4], al[4];
                    ldsm_x4(ah[0], ah[1], ah[2], ah[3], bAh + aAddr[mi] + kso);
                    ldsm_x4(al[0], al[1], al[2], al[3], bAl + aAddr[mi] + kso);
#pragma unroll
                    for (int ni = 0; ni < 4; ni++) {
                        mma_f16_f32acc(acc[mi][ni], ah, bh[ni]);
                        mma_f16_f16acc(hacc[mi][ni], ah, bl[ni]);
                        mma_f16_f16acc(hacc[mi][ni], al, bh[ni]);
                    }
                }
            }
        }

#pragma unroll
        for (int mi = 0; mi < 2; mi++) {
            const int row = bm + wm + mi * 16 + g;
#pragma unroll
            for (int ni = 0; ni < 4; ni++) {
                const int col = bn + wn + ni * 8 + tig * 2;
                if (col < N) {
                    float2 c0 = __half22float2(*(half2*)&hacc[mi][ni][0]);
                    float2 c1 = __half22float2(*(half2*)&hacc[mi][ni][1]);
                    *(float2*)(C + (size_t)row * ldc + col) =
                        make_float2(acc[mi][ni][0] + c0.x, acc[mi][ni][1] + c0.y);
                    *(float2*)(C + (size_t)(row + 8) * ldc + col) =
                        make_float2(acc[mi][ni][2] + c1.x, acc[mi][ni][3] + c1.y);
                }
            }
        }
    }
}

// ---------------------------------------------------------------------------
// Depthwise causal conv(k=4) + bias + SiLU -> xc hi/lo halves only;
// SiLU(z) -> g_zsT (b,d,l)
// ---------------------------------------------------------------------------
__global__ void conv_kernel(const float* __restrict__ xz,
                            const float* __restrict__ cw,
                            const float* __restrict__ cb,
                            __half* __restrict__ xch,
                            __half* __restrict__ xcl,
                            float* __restrict__ zsT)
{
    __shared__ float xs[35][33];
    __shared__ float zs[32][33];
    const int b = blockIdx.z;
    const int l0 = blockIdx.y << 5;
    const int d0 = blockIdx.x << 5;
    const int t = threadIdx.x;
    const int c = t & 31;
    const int r0 = t >> 5;

    for (int r = r0; r < 35; r += 8) {
        int l = l0 - 3 + r;
        xs[r][c] = (l >= 0) ? xz[((size_t)(b * L_SEQ + l) << 11) + d0 + c] : 0.f;
    }
    for (int r = r0; r < 32; r += 8) {
        float v = xz[((size_t)(b * L_SEQ + l0 + r) << 11) + DIMC + d0 + c];
        zs[r][c] = __fdividef(v, 1.f + __expf(-v));
    }
    __syncthreads();

    const float4 w = *(const float4*)(cw + (size_t)(d0 + c) * 4);
    const float bias = cb[d0 + c];
    for (int r = r0; r < 32; r += 8) {
        float v = w.x * xs[r][c] + w.y * xs[r + 1][c] + w.z * xs[r + 2][c]
                + w.w * xs[r + 3][c] + bias;
        v = __fdividef(v, 1.f + __expf(-v));
        const size_t idx = (size_t)(b * L_SEQ + l0 + r) * DIMC + d0 + c;
        __half hv = __float2half_rn(v);
        xch[idx] = hv;
        xcl[idx] = __float2half_rn(v - __half2float(hv));
    }
    __syncthreads();
    for (int r = r0; r < 32; r += 8) {
        zsT[(size_t)((b << 10) + d0 + r) * L_SEQ + l0 + c] = zs[c][r];
    }
}

// ---------------------------------------------------------------------------
// Build (b,d,l,{softplus(dt), xc}) interleaved stream + pack B/C (fused).
// xc reconstructed exactly from hi/lo halves.
// ---------------------------------------------------------------------------
__global__ void dtxc_kernel(const float* __restrict__ xdbl,
                            const __half* __restrict__ xch,
                            const __half* __restrict__ xcl,
                            float* __restrict__ dtxc,
                            float* __restrict__ bc)
{
    __shared__ float sdt[32][33];
    __shared__ float sxc[32][33];
    const int b = blockIdx.z;
    const int l0 = blockIdx.y << 5;
    const int d0 = blockIdx.x << 5;
    const int t = threadIdx.x;
    const int c = t & 31;
    const int r0 = t >> 5;

    for (int r = r0; r < 32; r += 8) {
        float v = xdbl[(size_t)(b * L_SEQ + l0 + r) * XDW + 2 * NST + d0 + c];
        sdt[r][c] = (v > 15.f) ? v : log1pf(__expf(v));
        const size_t idx = (size_t)(b * L_SEQ + l0 + r) * DIMC + d0 + c;
        sxc[r][c] = __half2float(xch[idx]) + __half2float(xcl[idx]);
    }
    if (d0 == 0) {
        int n = t & 15;
        int l2 = (l0 >> 1) + (t >> 4);
        const float* p = xdbl + (size_t)(b * L_SEQ + 2 * l2) * XDW;
        float4 v = make_float4(p[n], p[NST + n], p[XDW + n], p[XDW + NST + n]);
        *(float4*)(bc + ((size_t)b * (L_SEQ / 2) * NST + (size_t)l2 * NST + n) * 4) = v;
    }
    __syncthreads();
    for (int r = r0; r < 32; r += 8) {
        float2 v = make_float2(sdt[c][r], sxc[c][r]);
        *(float2*)(dtxc + ((size_t)((b << 10) + d0 + r) * L_SEQ + l0 + c) * 2) = v;
    }
}

// ---------------------------------------------------------------------------
// Selective scan, depth-2 prefetch via explicit x2 unroll (static registers).
// ---------------------------------------------------------------------------
__device__ __forceinline__ void scan_step4(
    float& h, float An, float Dv, bool root, int lane,
    const float4& cv0, const float4& cv1, const float4& cb01, const float4& cb23,
    const float4& cz, __half* yh, __half* yl, size_t ybase, int l)
{
    float4 yv;
    {
        float dA = __expf(An * cv0.x);
        h = fmaf(h, dA, cv0.x * cv0.y * cb01.x);
        float pr = h * cb01.y;
        pr += __shfl_xor_sync(0xffffffffu, pr, 1);
        pr += __shfl_xor_sync(0xffffffffu, pr, 2);
        pr += __shfl_xor_sync(0xffffffffu, pr, 4);
        pr += __shfl_xor_sync(0xffffffffu, pr, 8);
        yv.x = fmaf(Dv, cv0.y, pr) * cz.x;
    }
    {
        float dA = __expf(An * cv0.z);
        h = fmaf(h, dA, cv0.z * cv0.w * cb01.z);
        float pr = h * cb01.w;
        pr += __shfl_xor_sync(0xffffffffu, pr, 1);
        pr += __shfl_xor_sync(0xffffffffu, pr, 2);
        pr += __shfl_xor_sync(0xffffffffu, pr, 4);
        pr += __shfl_xor_sync(0xffffffffu, pr, 8);
        yv.y = fmaf(Dv, cv0.w, pr) * cz.y;
    }
    {
        float dA = __expf(An * cv1.x);
        h = fmaf(h, dA, cv1.x * cv1.y * cb23.x);
        float pr = h * cb23.y;
        pr += __shfl_xor_sync(0xffffffffu, pr, 1);
        pr += __shfl_xor_sync(0xffffffffu, pr, 2);
        pr += __shfl_xor_sync(0xffffffffu, pr, 4);
        pr += __shfl_xor_sync(0xffffffffu, pr, 8);
        yv.z = fmaf(Dv, cv1.y, pr) * cz.z;
    }
    {
        float dA = __expf(An * cv1.z);
        h = fmaf(h, dA, cv1.z * cv1.w * cb23.z);
        float pr = h * cb23.w;
        pr += __shfl_xor_sync(0xffffffffu, pr, 1);
        pr += __shfl_xor_sync(0xffffffffu, pr, 2);
        pr += __shfl_xor_sync(0xffffffffu, pr, 4);
        pr += __shfl_xor_sync(0xffffffffu, pr, 8);
        yv.w = fmaf(Dv, cv1.w, pr) * cz.w;
    }
    float u0 = __shfl_sync(0xffffffffu, yv.x, 16);
    float u1 = __shfl_sync(0xffffffffu, yv.y, 16);
    float u2 = __shfl_sync(0xffffffffu, yv.z, 16);
    float u3 = __shfl_sync(0xffffffffu, yv.w, 16);
    if (lane == 0) {
        float a[4] = {yv.x, yv.y, yv.z, yv.w};
        float bq[4] = {u0, u1, u2, u3};
#pragma unroll
        for (int q = 0; q < 4; q++) {
            __half ha = __float2half_rn(a[q]);
            __half hb = __float2half_rn(bq[q]);
            *(half2*)(yh + ybase + (size_t)(l + q) * DIMC) = __halves2half2(ha, hb);
            *(half2*)(yl + ybase + (size_t)(l + q) * DIMC) = __halves2half2(
                __float2half_rn(a[q] - __half2float(ha)),
                __float2half_rn(bq[q] - __half2float(hb)));
        }
    }
}

__global__ void scan_kernel(const float* __restrict__ dtxc,
                            const float* __restrict__ bc,
                            const float* __restrict__ zsT,
                            const float* __restrict__ Dp,
                            __half* __restrict__ yh,
                            __half* __restrict__ yl)
{
    const int warp = (blockIdx.x * blockDim.x + threadIdx.x) >> 5;
    const int lane = threadIdx.x & 31;
    const int b = warp >> 9;
    const int d = ((warp & 511) << 1) + (lane >> 4);
    const int n = lane & 15;
    const float An = -(float)(n + 1);
    const bool root = (n == 0);

    const size_t rowoff = (size_t)((b << 10) + d) * L_SEQ;
    const float* dxp = dtxc + rowoff * 2;
    const float* zp = zsT + rowoff;
    const float* bcp = bc + ((size_t)b * (L_SEQ / 2) * NST + n) * 4;
    const size_t ybase = ((size_t)b * L_SEQ) * DIMC + ((warp & 511) << 1);
    const float Dv = Dp[d];
    float h = 0.f;

    const float4 z4 = make_float4(0.f, 0.f, 0.f, 0.f);
    float4 a_v0 = *(const float4*)(dxp);
    float4 a_v1 = *(const float4*)(dxp + 4);
    float4 a_p01 = *(const float4*)(bcp);
    float4 a_p23 = *(const float4*)(bcp + 64);
    float4 a_z  = root ? *(const float4*)(zp) : z4;
    float4 b_v0 = *(const float4*)(dxp + 8);
    float4 b_v1 = *(const float4*)(dxp + 12);
    float4 b_p01 = *(const float4*)(bcp + 128);
    float4 b_p23 = *(const float4*)(bcp + 192);
    float4 b_z  = root ? *(const float4*)(zp + 4) : z4;

    for (int l = 0; l < L_SEQ; l += 8) {
        float4 cv0 = a_v0, cv1 = a_v1, cb01 = a_p01, cb23 = a_p23, cz = a_z;
        if (l + 8 < L_SEQ) {
            a_v0 = *(const float4*)(dxp + 2 * (l + 8));
            a_v1 = *(const float4*)(dxp + 2 * (l + 8) + 4);
            const float* q = bcp + (size_t)((l + 8) >> 1) * 64;
            a_p01 = *(const float4*)q;
            a_p23 = *(const float4*)(q + 64);
            if (root) a_z = *(const float4*)(zp + l + 8);
        }
        scan_step4(h, An, Dv, root, lane, cv0, cv1, cb01, cb23, cz, yh, yl, ybase, l);

        cv0 = b_v0; cv1 = b_v1; cb01 = b_p01; cb23 = b_p23; cz = b_z;
        if (l + 12 < L_SEQ) {
            b_v0 = *(const float4*)(dxp + 2 * (l + 12));
            b_v1 = *(const float4*)(dxp + 2 * (l + 12) + 4);
            const float* q = bcp + (size_t)((l + 12) >> 1) * 64;
            b_p01 = *(const float4*)q;
            b_p23 = *(const float4*)(q + 64);
            if (root) b_z = *(const float4*)(zp + l + 12);
        }
        scan_step4(h, An, Dv, root, lane, cv0, cv1, cb01, cb23, cz, yh, yl, ybase, l + 4);
    }
}

// ---------------------------------------------------------------------------
// kernel_launch
// ---------------------------------------------------------------------------
extern "C" void kernel_launch(void* const* d_in, const int* in_sizes, int n_in,
                              void* d_out, int out_size)
{
    (void)in_sizes; (void)n_in; (void)out_size;
    const float* x          = (const float*)d_in[0];
    const float* in_proj_w  = (const float*)d_in[1];
    const float* conv_w     = (const float*)d_in[2];
    const float* conv_b     = (const float*)d_in[3];
    const float* x_proj_w   = (const float*)d_in[4];
    const float* D_param    = (const float*)d_in[5];
    const float* out_proj_w = (const float*)d_in[6];
    float* out = (float*)d_out;

    float *xz, *xdbl, *zsT, *dtxc, *bcp;
    __half *xh, *xl, *wih, *wil, *wxh, *wxl, *woh, *wol, *xch, *xcl, *yh, *yl;
    cudaGetSymbolAddress((void**)&xz, g_xz);
    cudaGetSymbolAddress((void**)&xdbl, g_xdbl);
    cudaGetSymbolAddress((void**)&zsT, g_zsT);
    cudaGetSymbolAddress((void**)&dtxc, g_dtxc);
    cudaGetSymbolAddress((void**)&bcp, g_bc);
    cudaGetSymbolAddress((void**)&xh, g_xh);   cudaGetSymbolAddress((void**)&xl, g_xl);
    cudaGetSymbolAddress((void**)&wih, g_wih); cudaGetSymbolAddress((void**)&wil, g_wil);
    cudaGetSymbolAddress((void**)&wxh, g_wxh); cudaGetSymbolAddress((void**)&wxl, g_wxl);
    cudaGetSymbolAddress((void**)&woh, g_woh); cudaGetSymbolAddress((void**)&wol, g_wol);
    cudaGetSymbolAddress((void**)&xch, g_xch); cudaGetSymbolAddress((void**)&xcl, g_xcl);
    cudaGetSymbolAddress((void**)&yh, g_yh);   cudaGetSymbolAddress((void**)&yl, g_yl);

    const int SMEM_BYTES = NSTAGE * 4 * SEG * 2;  // 163840
    cudaFuncSetAttribute(gemm_f16s, cudaFuncAttributeMaxDynamicSharedMemorySize, SMEM_BYTES);

    // 0) split inputs + weights to fp16 hi/lo
    split_all_kernel<<<(N4_TOT + 255) / 256, 256>>>(x, in_proj_w, x_proj_w, out_proj_w,
                                                    xh, xl, wih, wil, wxh, wxl, woh, wol);

    // 1) xz = x @ in_proj_w^T   (4096 x 2048): 512 tiles, persistent
    gemm_f16s<<<NSM, 512, SMEM_BYTES>>>(xh, xl, wih, wil, xz, 2048, 2048, 16, 512);

    // 2) depthwise conv + silu -> xc hi/lo, silu(z) transpose
    conv_kernel<<<dim3(32, 64, 2), 256>>>(xz, conv_w, conv_b, xch, xcl, zsT);

    // 3) x_dbl = xc @ x_proj_w^T  (4096 x 1056): 288 tiles
    gemm_f16s<<<NSM, 512, SMEM_BYTES>>>(xch, xcl, wxh, wxl, xdbl, 1056, 1056, 9, 288);

    // 4) pack scan streams (dtxc + bc fused)
    dtxc_kernel<<<dim3(32, 64, 2), 256>>>(xdbl, xch, xcl, dtxc, bcp);

    // 5) selective scan -> y hi/lo halves, natural (b,l,d)
    scan_kernel<<<128, 256>>>(dtxc, bcp, zsT, D_param, yh, yl);

    // 6) out = y @ out_proj_w^T  (4096 x 1024): 256 tiles
    gemm_f16s<<<NSM, 512, SMEM_BYTES>>>(yh, yl, woh, wol, out, 1024, 1024, 8, 256);
}